// round 1
// baseline (speedup 1.0000x reference)
#include <cuda_runtime.h>
#include <math.h>

#define HDIM 128
#define MAXN 100000
#define POOL_SPLIT 8
#define NUM_GRAPHS 100

// ---------------- scratch (no allocation allowed) ----------------
__device__ float g_Y[MAXN * HDIM];
__device__ float g_hA[MAXN * HDIM];
__device__ float g_hB[MAXN * HDIM];
__device__ float g_ns[MAXN];
__device__ float g_nd[MAXN];
__device__ float g_outdeg[MAXN];
__device__ float g_indeg[MAXN];

// ---------------- degree / norm kernels ----------------
__global__ void init_deg_kernel(float* outdeg, float* indeg, int N) {
    int i = blockIdx.x * blockDim.x + threadIdx.x;
    if (i < N) { outdeg[i] = 1.0f; indeg[i] = 1.0f; }  // self-loop
}

__global__ void edge_deg_kernel(const int* __restrict__ src,
                                const int* __restrict__ dst,
                                float* outdeg, float* indeg, int E) {
    int i = blockIdx.x * blockDim.x + threadIdx.x;
    if (i < E) {
        atomicAdd(&outdeg[src[i]], 1.0f);
        atomicAdd(&indeg[dst[i]], 1.0f);
    }
}

__global__ void norms_kernel(const float* __restrict__ outdeg,
                             const float* __restrict__ indeg,
                             float* ns, float* nd, int N) {
    int i = blockIdx.x * blockDim.x + threadIdx.x;
    if (i < N) {
        ns[i] = rsqrtf(outdeg[i]);   // deg >= 1 always (self loop)
        nd[i] = rsqrtf(indeg[i]);
    }
}

// ---------------- GEMM: Y = (X * ns[:,None]) @ W ----------------
// Block: 64 rows of X, 256 threads. W(128x128) + Xtile(64x128) in dyn smem.
// Thread (rg=tid/32, cg=tid%32) computes rows rg*8..rg*8+7, cols cg*4..cg*4+3.
__global__ void gemm_scaled_kernel(const float* __restrict__ X,
                                   const float* __restrict__ ns,
                                   const float* __restrict__ W,
                                   float* __restrict__ Y, int N) {
    extern __shared__ float smem[];
    float* Ws = smem;                 // 128*128
    float* Xs = smem + HDIM * HDIM;   // 64*128

    const int tid = threadIdx.x;
    const int base = blockIdx.x * 64;

    // load W (4096 float4 / 256 threads = 16 iters)
    const float4* W4 = (const float4*)W;
    float4* Ws4 = (float4*)Ws;
    #pragma unroll
    for (int i = tid; i < HDIM * (HDIM / 4); i += 256)
        Ws4[i] = W4[i];

    // load X tile, scaled by ns (2048 float4 / 256 = 8 iters)
    const float4* X4 = (const float4*)X;
    float4* Xs4 = (float4*)Xs;
    #pragma unroll
    for (int i = tid; i < 64 * (HDIM / 4); i += 256) {
        int row = i >> 5;
        int c4  = i & 31;
        int gr  = base + row;
        float4 v = make_float4(0.f, 0.f, 0.f, 0.f);
        if (gr < N) {
            v = X4[gr * 32 + c4];
            float s = ns[gr];
            v.x *= s; v.y *= s; v.z *= s; v.w *= s;
        }
        Xs4[i] = v;
    }
    __syncthreads();

    const int rg = tid >> 5;   // 0..7
    const int cg = tid & 31;   // 0..31
    float acc[8][4];
    #pragma unroll
    for (int i = 0; i < 8; i++)
        #pragma unroll
        for (int j = 0; j < 4; j++) acc[i][j] = 0.f;

    const float4* WsV = (const float4*)Ws;
    #pragma unroll 4
    for (int k = 0; k < HDIM; k++) {
        float4 w = WsV[k * 32 + cg];
        #pragma unroll
        for (int i = 0; i < 8; i++) {
            float a = Xs[(rg * 8 + i) * HDIM + k];   // broadcast within warp
            acc[i][0] += a * w.x;
            acc[i][1] += a * w.y;
            acc[i][2] += a * w.z;
            acc[i][3] += a * w.w;
        }
    }

    float4* Y4 = (float4*)Y;
    #pragma unroll
    for (int i = 0; i < 8; i++) {
        int gr = base + rg * 8 + i;
        if (gr < N)
            Y4[gr * 32 + cg] = make_float4(acc[i][0], acc[i][1], acc[i][2], acc[i][3]);
    }
}

// ---------------- edge scatter: agg[dst] += Y[src] ----------------
// one warp per edge; lane handles 4 dims via red.global.add.v4.f32
__global__ void scatter_kernel(const float* __restrict__ Y,
                               const int* __restrict__ src,
                               const int* __restrict__ dst,
                               float* __restrict__ agg, int E) {
    int gt = blockIdx.x * blockDim.x + threadIdx.x;
    int w  = gt >> 5;
    int lane = gt & 31;
    if (w >= E) return;
    int s = src[w];
    int d = dst[w];
    float4 v = ((const float4*)Y)[s * 32 + lane];
    float* p = &agg[d * HDIM + lane * 4];
    asm volatile("red.global.add.v4.f32 [%0], {%1, %2, %3, %4};"
                 :: "l"(p), "f"(v.x), "f"(v.y), "f"(v.z), "f"(v.w)
                 : "memory");
}

// ---------------- epilogue: h = relu(agg * nd + b) ----------------
__global__ void epilogue_kernel(float* __restrict__ h,
                                const float* __restrict__ nd,
                                const float* __restrict__ b, int N) {
    int idx = blockIdx.x * blockDim.x + threadIdx.x;  // float4 index
    if (idx >= N * 32) return;
    int n  = idx >> 5;
    int c4 = idx & 31;
    float s = nd[n];
    float4 v = ((float4*)h)[idx];
    float4 bb = ((const float4*)b)[c4];
    v.x = fmaxf(v.x * s + bb.x, 0.f);
    v.y = fmaxf(v.y * s + bb.y, 0.f);
    v.z = fmaxf(v.z * s + bb.z, 0.f);
    v.w = fmaxf(v.w * s + bb.w, 0.f);
    ((float4*)h)[idx] = v;
}

// ---------------- output zero init ----------------
__global__ void zero_out_kernel(float* out, int n) {
    int i = blockIdx.x * blockDim.x + threadIdx.x;
    if (i < n) out[i] = 0.f;
}

// ---------------- pooling ----------------
// grid = NUM_GRAPHS * POOL_SPLIT blocks, 128 threads each (one per dim).
// graph_ids sorted -> binary search range. sum via atomicAdd, max via int
// atomicMax (valid: relu outputs >= 0, out zero-initialized).
__global__ void pool_kernel(const float* __restrict__ h,
                            const int* __restrict__ gid,
                            const float* __restrict__ Wp,
                            const float* __restrict__ bp,
                            float* __restrict__ out, int N) {
    const int g    = blockIdx.x / POOL_SPLIT;
    const int part = blockIdx.x % POOL_SPLIT;
    const int tid  = threadIdx.x;

    // binary search [start, end) of graph g in sorted gid
    int lo = 0, hi = N;
    while (lo < hi) { int m = (lo + hi) >> 1; if (gid[m] < g) lo = m + 1; else hi = m; }
    int start = lo;
    lo = start; hi = N;
    while (lo < hi) { int m = (lo + hi) >> 1; if (gid[m] < g + 1) lo = m + 1; else hi = m; }
    int end = lo;

    __shared__ float sWp[HDIM];
    __shared__ float red[4];
    __shared__ float sdot;
    sWp[tid] = Wp[tid];
    float bpv = bp[0];
    __syncthreads();

    float lsum = 0.f;
    float lmax = 0.f;
    const int lane = tid & 31;
    const int warp = tid >> 5;

    for (int n = start + part; n < end; n += POOL_SPLIT) {
        float val = h[n * HDIM + tid];
        float p = val * sWp[tid];
        #pragma unroll
        for (int o = 16; o > 0; o >>= 1)
            p += __shfl_down_sync(0xFFFFFFFFu, p, o);
        if (lane == 0) red[warp] = p;
        __syncthreads();
        if (tid == 0) sdot = red[0] + red[1] + red[2] + red[3] + bpv;
        __syncthreads();
        float w = 1.0f / (1.0f + expf(-sdot));
        lsum += val * w;
        lmax = fmaxf(lmax, val);
        __syncthreads();   // protect red/sdot for next iter
    }

    if (end > start) {
        atomicAdd(&out[g * 2 * HDIM + tid], lsum);
        atomicMax((int*)&out[g * 2 * HDIM + HDIM + tid], __float_as_int(lmax));
    }
}

// ---------------- launch ----------------
extern "C" void kernel_launch(void* const* d_in, const int* in_sizes, int n_in,
                              void* d_out, int out_size) {
    const float* node_feats = (const float*)d_in[0];
    const int*   src        = (const int*)d_in[1];
    const int*   dst        = (const int*)d_in[2];
    const int*   gid        = (const int*)d_in[3];
    const float* W1 = (const float*)d_in[4];  const float* b1 = (const float*)d_in[5];
    const float* W2 = (const float*)d_in[6];  const float* b2 = (const float*)d_in[7];
    const float* W3 = (const float*)d_in[8];  const float* b3 = (const float*)d_in[9];
    const float* Wp = (const float*)d_in[10]; const float* bp = (const float*)d_in[11];
    float* out = (float*)d_out;

    const int N = in_sizes[0] / HDIM;
    const int E = in_sizes[1];

    float *pY, *phA, *phB, *pns, *pnd, *pod, *pid_;
    cudaGetSymbolAddress((void**)&pY,  g_Y);
    cudaGetSymbolAddress((void**)&phA, g_hA);
    cudaGetSymbolAddress((void**)&phB, g_hB);
    cudaGetSymbolAddress((void**)&pns, g_ns);
    cudaGetSymbolAddress((void**)&pnd, g_nd);
    cudaGetSymbolAddress((void**)&pod, g_outdeg);
    cudaGetSymbolAddress((void**)&pid_, g_indeg);

    const int smem_gemm = (HDIM * HDIM + 64 * HDIM) * (int)sizeof(float);  // 96 KB
    cudaFuncSetAttribute(gemm_scaled_kernel,
                         cudaFuncAttributeMaxDynamicSharedMemorySize, smem_gemm);

    // degrees + norms
    init_deg_kernel<<<(N + 255) / 256, 256>>>(pod, pid_, N);
    edge_deg_kernel<<<(E + 255) / 256, 256>>>(src, dst, pod, pid_, E);
    norms_kernel<<<(N + 255) / 256, 256>>>(pod, pid_, pns, pnd, N);

    const int gemm_grid = (N + 63) / 64;
    const size_t feat_bytes = (size_t)N * HDIM * sizeof(float);
    const int scatter_blocks = (int)(((long long)E * 32 + 255) / 256);
    const int epi_blocks = (N * 32 + 255) / 256;

    const float* h_in = node_feats;
    float* h_out_layer[3] = {phA, phB, phA};
    const float* Ws[3] = {W1, W2, W3};
    const float* bs[3] = {b1, b2, b3};

    for (int l = 0; l < 3; l++) {
        float* hout = h_out_layer[l];
        gemm_scaled_kernel<<<gemm_grid, 256, smem_gemm>>>(h_in, pns, Ws[l], pY, N);
        // self-loop contribution initializes agg
        cudaMemcpyAsync(hout, pY, feat_bytes, cudaMemcpyDeviceToDevice);
        scatter_kernel<<<scatter_blocks, 256>>>(pY, src, dst, hout, E);
        epilogue_kernel<<<epi_blocks, 256>>>(hout, pnd, bs[l], N);
        h_in = hout;
    }

    // pooling
    zero_out_kernel<<<(out_size + 255) / 256, 256>>>(out, out_size);
    pool_kernel<<<NUM_GRAPHS * POOL_SPLIT, HDIM>>>(phA, gid, Wp, bp, out, N);
}

// round 2
// speedup vs baseline: 1.6622x; 1.6622x over previous
#include <cuda_runtime.h>
#include <math.h>

#define HDIM 128
#define MAXN 100000
#define MAXE 1600000
#define POOL_SPLIT 8
#define NUM_GRAPHS 100
#define SCAN_BLK 256
#define MAX_BLKS 512   // supports N up to 512*256 = 131072

// ---------------- scratch (no allocation allowed) ----------------
__device__ float g_Y[MAXN * HDIM];
__device__ float g_hA[MAXN * HDIM];
__device__ float g_hB[MAXN * HDIM];
__device__ float g_ns[MAXN];
__device__ float g_nd[MAXN];
__device__ int   g_odeg[MAXN];
__device__ int   g_ideg[MAXN];
__device__ int   g_off[MAXN];
__device__ int   g_cursor[MAXN];
__device__ int   g_csr_src[MAXE];
__device__ int   g_bsums[MAX_BLKS];

// ---------------- degree counting ----------------
__global__ void zero_deg_kernel(int* odeg, int* ideg, int N) {
    int i = blockIdx.x * blockDim.x + threadIdx.x;
    if (i < N) { odeg[i] = 0; ideg[i] = 0; }
}

__global__ void count_deg_kernel(const int* __restrict__ src,
                                 const int* __restrict__ dst,
                                 int* odeg, int* ideg, int E) {
    int i = blockIdx.x * blockDim.x + threadIdx.x;
    if (i < E) {
        atomicAdd(&odeg[src[i]], 1);
        atomicAdd(&ideg[dst[i]], 1);
    }
}

__global__ void norms_kernel(const int* __restrict__ odeg,
                             const int* __restrict__ ideg,
                             float* ns, float* nd, int N) {
    int i = blockIdx.x * blockDim.x + threadIdx.x;
    if (i < N) {
        ns[i] = rsqrtf((float)(odeg[i] + 1));   // +1 self-loop
        nd[i] = rsqrtf((float)(ideg[i] + 1));
    }
}

// ---------------- prefix sum (3 kernels) ----------------
__global__ void blocksum_kernel(const int* __restrict__ deg, int* bsums, int N) {
    __shared__ int s[SCAN_BLK];
    int i = blockIdx.x * SCAN_BLK + threadIdx.x;
    s[threadIdx.x] = (i < N) ? deg[i] : 0;
    __syncthreads();
    for (int o = SCAN_BLK / 2; o > 0; o >>= 1) {
        if (threadIdx.x < o) s[threadIdx.x] += s[threadIdx.x + o];
        __syncthreads();
    }
    if (threadIdx.x == 0) bsums[blockIdx.x] = s[0];
}

__global__ void scan_bsums_kernel(int* bsums, int nblk) {
    // single block, Hillis-Steele inclusive -> write exclusive
    __shared__ int s[MAX_BLKS];
    int t = threadIdx.x;
    int v = (t < nblk) ? bsums[t] : 0;
    s[t] = v;
    __syncthreads();
    for (int o = 1; o < MAX_BLKS; o <<= 1) {
        int add = (t >= o) ? s[t - o] : 0;
        __syncthreads();
        s[t] += add;
        __syncthreads();
    }
    if (t < nblk) bsums[t] = s[t] - v;   // exclusive
}

__global__ void write_offsets_kernel(const int* __restrict__ deg,
                                     const int* __restrict__ bsums,
                                     int* off, int* cursor, int N) {
    __shared__ int s[SCAN_BLK];
    int i = blockIdx.x * SCAN_BLK + threadIdx.x;
    int t = threadIdx.x;
    int v = (i < N) ? deg[i] : 0;
    s[t] = v;
    __syncthreads();
    for (int o = 1; o < SCAN_BLK; o <<= 1) {
        int add = (t >= o) ? s[t - o] : 0;
        __syncthreads();
        s[t] += add;
        __syncthreads();
    }
    if (i < N) {
        int ofs = bsums[blockIdx.x] + s[t] - v;   // exclusive
        off[i] = ofs;
        cursor[i] = ofs;
    }
}

__global__ void fill_csr_kernel(const int* __restrict__ src,
                                const int* __restrict__ dst,
                                int* cursor, int* csr_src, int E) {
    int i = blockIdx.x * blockDim.x + threadIdx.x;
    if (i < E) {
        int slot = atomicAdd(&cursor[dst[i]], 1);
        csr_src[slot] = src[i];
    }
}

// ---------------- GEMM: Y = (X * ns[:,None]) @ W ----------------
__global__ void gemm_scaled_kernel(const float* __restrict__ X,
                                   const float* __restrict__ ns,
                                   const float* __restrict__ W,
                                   float* __restrict__ Y, int N) {
    extern __shared__ float smem[];
    float* Ws = smem;                 // 128*128
    float* Xs = smem + HDIM * HDIM;   // 64*128

    const int tid = threadIdx.x;
    const int base = blockIdx.x * 64;

    const float4* W4 = (const float4*)W;
    float4* Ws4 = (float4*)Ws;
    #pragma unroll
    for (int i = tid; i < HDIM * (HDIM / 4); i += 256)
        Ws4[i] = W4[i];

    const float4* X4 = (const float4*)X;
    float4* Xs4 = (float4*)Xs;
    #pragma unroll
    for (int i = tid; i < 64 * (HDIM / 4); i += 256) {
        int row = i >> 5;
        int c4  = i & 31;
        int gr  = base + row;
        float4 v = make_float4(0.f, 0.f, 0.f, 0.f);
        if (gr < N) {
            v = X4[gr * 32 + c4];
            float s = ns[gr];
            v.x *= s; v.y *= s; v.z *= s; v.w *= s;
        }
        Xs4[i] = v;
    }
    __syncthreads();

    const int rg = tid >> 5;
    const int cg = tid & 31;
    float acc[8][4];
    #pragma unroll
    for (int i = 0; i < 8; i++)
        #pragma unroll
        for (int j = 0; j < 4; j++) acc[i][j] = 0.f;

    const float4* WsV = (const float4*)Ws;
    #pragma unroll 4
    for (int k = 0; k < HDIM; k++) {
        float4 w = WsV[k * 32 + cg];
        #pragma unroll
        for (int i = 0; i < 8; i++) {
            float a = Xs[(rg * 8 + i) * HDIM + k];
            acc[i][0] += a * w.x;
            acc[i][1] += a * w.y;
            acc[i][2] += a * w.z;
            acc[i][3] += a * w.w;
        }
    }

    float4* Y4 = (float4*)Y;
    #pragma unroll
    for (int i = 0; i < 8; i++) {
        int gr = base + rg * 8 + i;
        if (gr < N)
            Y4[gr * 32 + cg] = make_float4(acc[i][0], acc[i][1], acc[i][2], acc[i][3]);
    }
}

// ---------------- fused gather + epilogue ----------------
// one warp per dst node, lane = float4 of 4 dims.
// h[n] = relu((Y[n] + sum_{s in in(n)} Y[s]) * nd[n] + b)
__global__ void gather_epilogue_kernel(const float* __restrict__ Y,
                                       const int* __restrict__ off,
                                       const int* __restrict__ ideg,
                                       const int* __restrict__ csr_src,
                                       const float* __restrict__ nd,
                                       const float* __restrict__ b,
                                       float* __restrict__ h, int N) {
    int gt = blockIdx.x * blockDim.x + threadIdx.x;
    int n = gt >> 5;
    int lane = threadIdx.x & 31;
    if (n >= N) return;

    const float4* Y4 = (const float4*)Y;
    float4 acc = Y4[n * 32 + lane];   // self-loop contribution
    int o = off[n];
    int d = ideg[n];

    int e = 0;
    for (; e + 4 <= d; e += 4) {
        int s0 = csr_src[o + e + 0];
        int s1 = csr_src[o + e + 1];
        int s2 = csr_src[o + e + 2];
        int s3 = csr_src[o + e + 3];
        float4 v0 = __ldg(&Y4[s0 * 32 + lane]);
        float4 v1 = __ldg(&Y4[s1 * 32 + lane]);
        float4 v2 = __ldg(&Y4[s2 * 32 + lane]);
        float4 v3 = __ldg(&Y4[s3 * 32 + lane]);
        acc.x += v0.x + v1.x + v2.x + v3.x;
        acc.y += v0.y + v1.y + v2.y + v3.y;
        acc.z += v0.z + v1.z + v2.z + v3.z;
        acc.w += v0.w + v1.w + v2.w + v3.w;
    }
    for (; e < d; e++) {
        int s = csr_src[o + e];
        float4 v = __ldg(&Y4[s * 32 + lane]);
        acc.x += v.x; acc.y += v.y; acc.z += v.z; acc.w += v.w;
    }

    float sc = nd[n];
    float4 bb = ((const float4*)b)[lane];
    acc.x = fmaxf(acc.x * sc + bb.x, 0.f);
    acc.y = fmaxf(acc.y * sc + bb.y, 0.f);
    acc.z = fmaxf(acc.z * sc + bb.z, 0.f);
    acc.w = fmaxf(acc.w * sc + bb.w, 0.f);
    ((float4*)h)[n * 32 + lane] = acc;
}

// ---------------- output zero init ----------------
__global__ void zero_out_kernel(float* out, int n) {
    int i = blockIdx.x * blockDim.x + threadIdx.x;
    if (i < n) out[i] = 0.f;
}

// ---------------- pooling ----------------
__global__ void pool_kernel(const float* __restrict__ h,
                            const int* __restrict__ gid,
                            const float* __restrict__ Wp,
                            const float* __restrict__ bp,
                            float* __restrict__ out, int N) {
    const int g    = blockIdx.x / POOL_SPLIT;
    const int part = blockIdx.x % POOL_SPLIT;
    const int tid  = threadIdx.x;

    int lo = 0, hi = N;
    while (lo < hi) { int m = (lo + hi) >> 1; if (gid[m] < g) lo = m + 1; else hi = m; }
    int start = lo;
    lo = start; hi = N;
    while (lo < hi) { int m = (lo + hi) >> 1; if (gid[m] < g + 1) lo = m + 1; else hi = m; }
    int end = lo;

    __shared__ float sWp[HDIM];
    __shared__ float red[4];
    __shared__ float sdot;
    sWp[tid] = Wp[tid];
    float bpv = bp[0];
    __syncthreads();

    float lsum = 0.f;
    float lmax = 0.f;
    const int lane = tid & 31;
    const int warp = tid >> 5;

    for (int n = start + part; n < end; n += POOL_SPLIT) {
        float val = h[n * HDIM + tid];
        float p = val * sWp[tid];
        #pragma unroll
        for (int o = 16; o > 0; o >>= 1)
            p += __shfl_down_sync(0xFFFFFFFFu, p, o);
        if (lane == 0) red[warp] = p;
        __syncthreads();
        if (tid == 0) sdot = red[0] + red[1] + red[2] + red[3] + bpv;
        __syncthreads();
        float w = 1.0f / (1.0f + expf(-sdot));
        lsum += val * w;
        lmax = fmaxf(lmax, val);
        __syncthreads();
    }

    if (end > start) {
        atomicAdd(&out[g * 2 * HDIM + tid], lsum);
        atomicMax((int*)&out[g * 2 * HDIM + HDIM + tid], __float_as_int(lmax));
    }
}

// ---------------- launch ----------------
extern "C" void kernel_launch(void* const* d_in, const int* in_sizes, int n_in,
                              void* d_out, int out_size) {
    const float* node_feats = (const float*)d_in[0];
    const int*   src        = (const int*)d_in[1];
    const int*   dst        = (const int*)d_in[2];
    const int*   gid        = (const int*)d_in[3];
    const float* W1 = (const float*)d_in[4];  const float* b1 = (const float*)d_in[5];
    const float* W2 = (const float*)d_in[6];  const float* b2 = (const float*)d_in[7];
    const float* W3 = (const float*)d_in[8];  const float* b3 = (const float*)d_in[9];
    const float* Wp = (const float*)d_in[10]; const float* bp = (const float*)d_in[11];
    float* out = (float*)d_out;

    const int N = in_sizes[0] / HDIM;
    const int E = in_sizes[1];

    float *pY, *phA, *phB, *pns, *pnd;
    int *pod, *pid_, *poff, *pcur, *pcsr, *pbs;
    cudaGetSymbolAddress((void**)&pY,  g_Y);
    cudaGetSymbolAddress((void**)&phA, g_hA);
    cudaGetSymbolAddress((void**)&phB, g_hB);
    cudaGetSymbolAddress((void**)&pns, g_ns);
    cudaGetSymbolAddress((void**)&pnd, g_nd);
    cudaGetSymbolAddress((void**)&pod, g_odeg);
    cudaGetSymbolAddress((void**)&pid_, g_ideg);
    cudaGetSymbolAddress((void**)&poff, g_off);
    cudaGetSymbolAddress((void**)&pcur, g_cursor);
    cudaGetSymbolAddress((void**)&pcsr, g_csr_src);
    cudaGetSymbolAddress((void**)&pbs, g_bsums);

    const int smem_gemm = (HDIM * HDIM + 64 * HDIM) * (int)sizeof(float);  // 96 KB
    cudaFuncSetAttribute(gemm_scaled_kernel,
                         cudaFuncAttributeMaxDynamicSharedMemorySize, smem_gemm);

    const int nblk_scan = (N + SCAN_BLK - 1) / SCAN_BLK;

    // --- CSR build + norms ---
    zero_deg_kernel<<<(N + 255) / 256, 256>>>(pod, pid_, N);
    count_deg_kernel<<<(E + 255) / 256, 256>>>(src, dst, pod, pid_, E);
    norms_kernel<<<(N + 255) / 256, 256>>>(pod, pid_, pns, pnd, N);
    blocksum_kernel<<<nblk_scan, SCAN_BLK>>>(pid_, pbs, N);
    scan_bsums_kernel<<<1, MAX_BLKS>>>(pbs, nblk_scan);
    write_offsets_kernel<<<nblk_scan, SCAN_BLK>>>(pid_, pbs, poff, pcur, N);
    fill_csr_kernel<<<(E + 255) / 256, 256>>>(src, dst, pcur, pcsr, E);

    const int gemm_grid = (N + 63) / 64;
    const int gather_blocks = (int)(((long long)N * 32 + 255) / 256);

    const float* h_in = node_feats;
    float* h_out_layer[3] = {phA, phB, phA};
    const float* Ws[3] = {W1, W2, W3};
    const float* bs[3] = {b1, b2, b3};

    for (int l = 0; l < 3; l++) {
        float* hout = h_out_layer[l];
        gemm_scaled_kernel<<<gemm_grid, 256, smem_gemm>>>(h_in, pns, Ws[l], pY, N);
        gather_epilogue_kernel<<<gather_blocks, 256>>>(pY, poff, pid_, pcsr,
                                                       pnd, bs[l], hout, N);
        h_in = hout;
    }

    // pooling
    zero_out_kernel<<<(out_size + 255) / 256, 256>>>(out, out_size);
    pool_kernel<<<NUM_GRAPHS * POOL_SPLIT, HDIM>>>(phA, gid, Wp, bp, out, N);
}